// round 1
// baseline (speedup 1.0000x reference)
#include <cuda_runtime.h>
#include <cstdint>

// Shapes fixed by the problem instance:
// B=1, H=32, L=8192, D=128, S=16384, GLOBAL_TOKENS=4
// keep[i] = i (i<4) else i+ (S-L) = i+8192
// out layout (float32): k_out [H,L,D] | v_out [H,L,D] | pos_out [L]

#define H_ 32
#define L_ 8192
#define D_ 128
#define S_ 16384
#define GTOK 4
#define F4_ROW (D_ / 4)                 // 32 float4 per row
#define F4_PER_HEAD_DST (L_ * F4_ROW)   // 262144
#define F4_PER_HEAD_SRC (S_ * F4_ROW)   // 524288
#define NK ((size_t)H_ * L_ * D_)       // 33554432 floats per tensor

__global__ void kvwindow_gather_kernel(const float4* __restrict__ k_val,
                                       const float4* __restrict__ v_val,
                                       const int*    __restrict__ input_pos,
                                       float4*       __restrict__ out4) {
    const int idx = blockIdx.x * blockDim.x + threadIdx.x;  // 0 .. F4_PER_HEAD_DST-1
    const int h   = blockIdx.y;                              // 0 .. 31
    const int z   = blockIdx.z;                              // 0 = K, 1 = V

    // row i < GTOK  <=>  idx < GTOK * F4_ROW (=128)
    const int src_shift = (idx < GTOK * F4_ROW) ? 0 : ((S_ - L_) * F4_ROW);
    const size_t src = (size_t)h * F4_PER_HEAD_SRC + (size_t)idx + src_shift;
    const size_t dst = (size_t)z * (NK / 4) + (size_t)h * F4_PER_HEAD_DST + idx;

    const float4* __restrict__ srcp = z ? v_val : k_val;
    out4[dst] = srcp[src];

    // Fold pos_out into the (z=0, h=0) slice: first L_ threads each write one element.
    if (z == 0 && h == 0 && idx < L_) {
        float* pos_out = reinterpret_cast<float*>(out4) + 2 * NK;
        const int j = idx;
        int p = input_pos[(j < GTOK) ? j : (j + (S_ - L_))];
        if (p >= 0 && p < GTOK) p = 1000000000;
        pos_out[j] = (float)p;
    }
}

extern "C" void kernel_launch(void* const* d_in, const int* in_sizes, int n_in,
                              void* d_out, int out_size) {
    // metadata order: k_cache, v_cache, k_val, v_val, pos, input_pos
    const float4* k_val = (const float4*)d_in[2];
    const float4* v_val = (const float4*)d_in[3];
    const int* input_pos = (const int*)d_in[5];
    float4* out4 = (float4*)d_out;

    dim3 block(256);
    dim3 grid(F4_PER_HEAD_DST / 256, H_, 2);  // (1024, 32, 2)
    kvwindow_gather_kernel<<<grid, block>>>(k_val, v_val, input_pos, out4);
}

// round 3
// speedup vs baseline: 1.0207x; 1.0207x over previous
#include <cuda_runtime.h>
#include <cstdint>

// B=1, H=32, L=8192, D=128, S=16384, GLOBAL_TOKENS=4
// keep[i] = i (i<4) else i+8192
// out layout (float32): k_out [H,L,D] | v_out [H,L,D] | pos_out [L]

#define H_ 32
#define L_ 8192
#define D_ 128
#define S_ 16384
#define GTOK 4
#define F4_ROW (D_ / 4)                 // 32 float4 per row
#define F4_PER_HEAD_DST (L_ * F4_ROW)   // 262144
#define F4_PER_HEAD_SRC (S_ * F4_ROW)   // 524288
#define NK ((size_t)H_ * L_ * D_)       // 33554432 floats per tensor

#define UNROLL 4
#define TPB 256
#define TILE (TPB * UNROLL)             // 1024 float4 per block-tile

__global__ __launch_bounds__(TPB) void kvwindow_gather_kernel(
        const float4* __restrict__ k_val,
        const float4* __restrict__ v_val,
        const int*    __restrict__ input_pos,
        float4*       __restrict__ out4) {
    const int h = blockIdx.y;     // 0..31
    const int z = blockIdx.z;     // 0 = K, 1 = V

    const int base = blockIdx.x * TILE + threadIdx.x;   // within head (float4 units)
    const float4* __restrict__ srcp = z ? v_val : k_val;
    const size_t src_head = (size_t)h * F4_PER_HEAD_SRC;
    const size_t dst_head = (size_t)z * (NK / 4) + (size_t)h * F4_PER_HEAD_DST;

    // Front-batched independent loads (MLP = UNROLL)
    float4 r[UNROLL];
#pragma unroll
    for (int u = 0; u < UNROLL; u++) {
        const int idx = base + u * TPB;
        const int src_shift = (idx < GTOK * F4_ROW) ? 0 : ((S_ - L_) * F4_ROW);
        r[u] = __ldcs(srcp + src_head + (size_t)idx + src_shift);
    }
#pragma unroll
    for (int u = 0; u < UNROLL; u++) {
        const int idx = base + u * TPB;
        __stcs(out4 + dst_head + idx, r[u]);
    }

    // pos_out: fold into (z=0, h=0, first blocks) — covers j in [0, L_)
    if (z == 0 && h == 0 && base < L_) {
#pragma unroll
        for (int u = 0; u < UNROLL; u++) {
            const int j = base + u * TPB;
            if (j < L_) {
                float* pos_out = reinterpret_cast<float*>(out4) + 2 * NK;
                int p = input_pos[(j < GTOK) ? j : (j + (S_ - L_))];
                if (p >= 0 && p < GTOK) p = 1000000000;
                pos_out[j] = (float)p;
            }
        }
    }
}

extern "C" void kernel_launch(void* const* d_in, const int* in_sizes, int n_in,
                              void* d_out, int out_size) {
    // metadata order: k_cache, v_cache, k_val, v_val, pos, input_pos
    const float4* k_val = (const float4*)d_in[2];
    const float4* v_val = (const float4*)d_in[3];
    const int* input_pos = (const int*)d_in[5];
    float4* out4 = (float4*)d_out;

    dim3 block(TPB);
    dim3 grid(F4_PER_HEAD_DST / TILE, H_, 2);  // (256, 32, 2) = 16384 blocks
    kvwindow_gather_kernel<<<grid, block>>>(k_val, v_val, input_pos, out4);
}